// round 2
// baseline (speedup 1.0000x reference)
#include <cuda_runtime.h>
#include <stdint.h>
#include <math.h>

#define NKPT 21
#define NANCH 12
#define BMAX 32
#define MAXA (12*128*128)

// Reference keypoint pose (21 x 2), float32 exactly as in the reference.
__constant__ float c_ref[NKPT*2] = {
 213.33335876464844f, 124.50563049316406f,
 190.504638671875f,   115.11840057373047f,
 169.9791717529297f,  101.77180480957031f,
 146.72341918945312f,  96.25749206542969f,
 128.86770629882812f,  87.2344970703125f,
 150.34292602539062f, 101.61070251464844f,
 119.29926300048828f,  98.73982238769531f,
 100.03463745117188f,  99.74459838867188f,
  82.62400817871094f, 101.2509536743164f,
 148.91049194335938f, 112.71517181396484f,
 114.37303161621094f, 113.20121002197266f,
  91.90096282958984f, 116.49812316894531f,
  74.75020599365234f, 119.37875366210938f,
 149.59658813476562f, 124.09295654296875f,
 119.72419738769531f, 126.36898040771484f,
  99.59107208251953f, 129.40196228027344f,
  82.82524108886719f, 131.584228515625f,
 154.55911254882812f, 135.07681274414062f,
 133.8833770751953f,  140.85983276367188f,
 120.45906066894531f, 145.40306091308594f,
 106.21541595458984f, 150.072265625f
};

// Per-(b,a) decision code: 0=neg(inside), 1=left, 2=right, 3=outside.
__device__ uint8_t g_dec[(size_t)BMAX * MAXA];

// -----------------------------------------------------------------------------
// Phase A: one thread per anchor. Computes anchor pose (staged in smem for a
// coalesced cooperative write), inside flag, OKS sims vs all (b, hand) GTs,
// labels, and the 1-byte decision code.
// -----------------------------------------------------------------------------
__global__ void __launch_bounds__(128) phaseA_kernel(
    const float* __restrict__ gt,   // [B,2,21,3] flattened
    const int*   __restrict__ ht,   // [B,2]
    const int*   __restrict__ fhp,  // scalar (may be null)
    const int*   __restrict__ fwp,  // scalar (may be null)
    float* __restrict__ out,        // full output buffer
    int B, int A)
{
    __shared__ float s_gt[BMAX*2*NKPT*3];   // 16 KB max
    __shared__ float s_negcoef[BMAX*2];
    __shared__ float s_nvinv[BMAX*2];
    __shared__ float sA[128*43];            // padded (43) -> conflict-free

    const int tid = threadIdx.x;

    int feat_w, feat_h;
    if (fwp) { feat_w = *fwp; feat_h = *fhp; }
    else {
        int pos = A / NANCH;
        feat_w = (int)rintf(sqrtf((float)pos));
        feat_h = pos / feat_w;
    }

    // Load GT into shared
    const int ngt = B*2*NKPT*3;
    for (int i = tid; i < ngt; i += 128) s_gt[i] = gt[i];
    __syncthreads();

    // Per-(b,hand) OKS coefficients
    if (tid < B*2) {
        const float* g = s_gt + tid*NKPT*3;
        float xmn = 3.4e38f, xmx = -3.4e38f, ymn = 3.4e38f, ymx = -3.4e38f, nv = 0.f;
        #pragma unroll
        for (int k = 0; k < NKPT; k++) {
            float x = g[3*k], y = g[3*k+1];
            xmn = fminf(xmn, x); xmx = fmaxf(xmx, x);
            ymn = fminf(ymn, y); ymx = fmaxf(ymx, y);
            nv += (g[3*k+2] > 0.f) ? 1.f : 0.f;
        }
        float area = (xmx - xmn) * (ymx - ymn);
        float s2   = fmaxf(area, 1.f);
        s_negcoef[tid] = -1.f / (2.f * s2 * 0.01f);   // k2 = (2*0.05)^2 = 0.01
        s_nvinv[tid]   = 1.f / fmaxf(nv, 1.f);
    }

    const int a = blockIdx.x * 128 + tid;
    const bool valid = (a < A);

    float ax[NKPT], ay[NKPT];
    bool inside = true;

    if (valid) {
        int j   = a % NANCH;
        int pos = a / NANCH;
        int ix  = pos % feat_w;
        int iy  = pos / feat_w;

        // shifts computed in double then cast (matches numpy float64->float32)
        float shx = (float)((double)ix * (256.0 / (double)feat_w));
        float shy = (float)((double)iy * (256.0 / (double)feat_h));

        int si = j >> 2, oi = j & 3;
        float sc = (si == 0) ? 0.25f : ((si == 1) ? 0.5f : 1.0f);
        double th = (double)(oi * 90) * (M_PI / 180.0);
        float cth = (float)cos(th), sth = (float)sin(th);

        // center of REF_POSE (double accumulate for accuracy)
        double mx = 0.0, my = 0.0;
        #pragma unroll
        for (int k = 0; k < NKPT; k++) { mx += (double)c_ref[2*k]; my += (double)c_ref[2*k+1]; }
        float cx = (float)(mx / 21.0), cy = (float)(my / 21.0);

        #pragma unroll
        for (int k = 0; k < NKPT; k++) {
            float vx = c_ref[2*k]   - cx;
            float vy = c_ref[2*k+1] - cy;
            float bx = cx + sc * (vx*cth - vy*sth);
            float by = cy + sc * (vx*sth + vy*cth);
            float px = bx + shx;
            float py = by + shy;
            ax[k] = px; ay[k] = py;
            sA[tid*43 + 2*k]   = px;
            sA[tid*43 + 2*k+1] = py;
            inside = inside && (px >= 0.f) && (py >= 0.f) && (px < 256.f) && (py < 256.f);
        }
        // inside output (index A*42 + a)
        out[(size_t)A*42 + a] = inside ? 1.f : 0.f;
    }
    __syncthreads();

    if (valid) {
        float* labels = out + (size_t)A*43;
        for (int b = 0; b < B; b++) {
            float sim0, sim1;
            #pragma unroll
            for (int h = 0; h < 2; h++) {
                const float* g = s_gt + (b*2 + h)*NKPT*3;
                float nc  = s_negcoef[b*2 + h];
                float acc = 0.f;
                #pragma unroll
                for (int k = 0; k < NKPT; k++) {
                    float dx = ax[k] - g[3*k];
                    float dy = ay[k] - g[3*k+1];
                    float d2 = dx*dx + dy*dy;
                    float e  = __expf(d2 * nc);
                    acc += (g[3*k+2] > 0.f) ? e : 0.f;
                }
                float s = acc * s_nvinv[b*2 + h];
                if (h == 0) sim0 = s; else sim1 = s;
            }
            bool am0 = (sim0 >= sim1);               // argmax tie -> first index
            float mxs = fmaxf(sim0, sim1);
            bool right = am0  && (mxs > 0.5f) && (ht[2*b]   == 1) && inside;
            bool left  = !am0 && (mxs > 0.5f) && (ht[2*b+1] == 1) && inside;

            float l0, l1, l2;
            if (inside) {
                l0 = left  ? 1.f : 0.f;
                l2 = right ? 1.f : 0.f;
                l1 = (!left && !right) ? 1.f : 0.f;
            } else {
                l0 = l1 = l2 = -1.f;
            }
            size_t lb = ((size_t)b*A + a) * 3;
            labels[lb]   = l0;
            labels[lb+1] = l1;
            labels[lb+2] = l2;

            g_dec[(size_t)b*A + a] = inside ? (right ? 2 : (left ? 1 : 0)) : 3;
        }
    }

    // Cooperative, fully coalesced anchor write from padded smem
    {
        int a0    = blockIdx.x * 128;
        int cnt   = min(128, A - a0);
        int total = cnt * 42;
        size_t base = (size_t)a0 * 42;
        for (int i = tid; i < total; i += 128) {
            int la = i / 42;
            int e  = i - la * 42;
            out[base + i] = sA[la*43 + e];
        }
    }
}

// -----------------------------------------------------------------------------
// Phase C: one thread per (b, a, k) writes one float2 offset. Perfectly
// coalesced stores; anchor re-reads hit L2 (8 MB, reused 16x); decision byte
// broadcast across the 21 kpts of an anchor.
// -----------------------------------------------------------------------------
__global__ void __launch_bounds__(256) phaseC_kernel(
    const float* __restrict__ gt,       // [B,2,21,3]
    const float* __restrict__ anchors,  // == out base, [A,21,2]
    float2* __restrict__ ofs,           // [B,A,21] float2
    int A)
{
    int idx = blockIdx.x * 256 + threadIdx.x;   // over A*21
    int nak = A * NKPT;
    if (idx >= nak) return;
    int b = blockIdx.y;
    int a = idx / NKPT;
    int k = idx - a * NKPT;

    uint8_t d = g_dec[(size_t)b*A + a];
    float2 r;
    if (d == 3) {                   // outside -> 0
        r.x = 0.f; r.y = 0.f;
    } else {
        float2 an = ((const float2*)anchors)[idx];   // a*21 + k == idx
        float tx = 0.f, ty = 0.f;
        if (d != 0) {               // assigned -> gt - anchor; neg -> -anchor
            int h = (d == 2) ? 0 : 1;
            const float* g = gt + ((size_t)(b*2 + h)*NKPT + k)*3;
            tx = g[0]; ty = g[1];
        }
        r.x = tx - an.x;
        r.y = ty - an.y;
    }
    ofs[(size_t)b*nak + idx] = r;
}

extern "C" void kernel_launch(void* const* d_in, const int* in_sizes, int n_in,
                              void* d_out, int out_size)
{
    const float* gt = (const float*)d_in[0];
    const int*   ht = (const int*)d_in[1];
    const int*   fh = (n_in >= 4) ? (const int*)d_in[2] : nullptr;
    const int*   fw = (n_in >= 4) ? (const int*)d_in[3] : nullptr;
    float* out = (float*)d_out;

    int B = in_sizes[0] / (2*NKPT*3);              // pose_gt has B*42*3 elems
    if (B < 1) B = 1;
    if (B > BMAX) B = BMAX;
    long long denom = 42 + 1 + 3LL*B + 42LL*B;     // floats per anchor in output
    int A = (int)((long long)out_size / denom);

    int blocksA = (A + 127) / 128;
    phaseA_kernel<<<blocksA, 128>>>(gt, ht, fh, fw, out, B, A);

    float2* ofs = (float2*)(out + (size_t)A*43 + (size_t)3*B*A);
    dim3 gridC((A*NKPT + 255) / 256, B);
    phaseC_kernel<<<gridC, 256>>>(gt, out, ofs, A);
}

// round 3
// speedup vs baseline: 1.2818x; 1.2818x over previous
#include <cuda_runtime.h>
#include <stdint.h>
#include <math.h>

#define NKPT 21
#define NANCH 12
#define BMAX 32
#define MAXA (12*128*128)
#define CTILE 64

// Reference keypoint pose (21 x 2), float32 exactly as in the reference.
__constant__ float c_ref[NKPT*2] = {
 213.33335876464844f, 124.50563049316406f,
 190.504638671875f,   115.11840057373047f,
 169.9791717529297f,  101.77180480957031f,
 146.72341918945312f,  96.25749206542969f,
 128.86770629882812f,  87.2344970703125f,
 150.34292602539062f, 101.61070251464844f,
 119.29926300048828f,  98.73982238769531f,
 100.03463745117188f,  99.74459838867188f,
  82.62400817871094f, 101.2509536743164f,
 148.91049194335938f, 112.71517181396484f,
 114.37303161621094f, 113.20121002197266f,
  91.90096282958984f, 116.49812316894531f,
  74.75020599365234f, 119.37875366210938f,
 149.59658813476562f, 124.09295654296875f,
 119.72419738769531f, 126.36898040771484f,
  99.59107208251953f, 129.40196228027344f,
  82.82524108886719f, 131.584228515625f,
 154.55911254882812f, 135.07681274414062f,
 133.8833770751953f,  140.85983276367188f,
 120.45906066894531f, 145.40306091308594f,
 106.21541595458984f, 150.072265625f
};

// Per-(b,a) decision code: 0=neg(inside), 1=left, 2=right, 3=outside.
__device__ uint8_t g_dec[(size_t)BMAX * MAXA];

__device__ __forceinline__ float ex2f(float x) {
    float y; asm("ex2.approx.f32 %0, %1;" : "=f"(y) : "f"(x)); return y;
}

// -----------------------------------------------------------------------------
// Phase A: one thread per anchor.
// -----------------------------------------------------------------------------
__global__ void __launch_bounds__(128) phaseA_kernel(
    const float* __restrict__ gt,   // [B,2,21,3]
    const int*   __restrict__ ht,   // [B,2]
    const int*   __restrict__ fhp,
    const int*   __restrict__ fwp,
    float* __restrict__ out,
    int B, int A)
{
    __shared__ float sA[128*43];            // anchors (padded); also scratch for raw gt
    __shared__ float s_gxy[BMAX*2*42];      // packed xy per (b,hand)
    __shared__ float s_nc[BMAX*2];          // -1.4427/(2*s2*k2)
    __shared__ float s_nvinv[BMAX*2];
    __shared__ unsigned s_mask[BMAX*2];     // visibility bits
    __shared__ int s_ht[BMAX*2];

    const int tid = threadIdx.x;

    int feat_w, feat_h;
    if (fwp) { feat_w = *fwp; feat_h = *fhp; }
    else {
        int pos = A / NANCH;
        feat_w = (int)rintf(sqrtf((float)pos));
        feat_h = pos / feat_w;
    }

    // 1) raw gt -> sA scratch
    const int ngt = B*2*NKPT*3;             // <= 4032, fits in sA (5504)
    for (int i = tid; i < ngt; i += 128) sA[i] = gt[i];
    if (tid < B*2) s_ht[tid] = ht[tid];
    __syncthreads();

    // 2) pack xy + coefficients + vis mask
    for (int i = tid; i < B*2*42; i += 128) {
        int b2 = i / 42, e = i - b2*42;
        s_gxy[i] = sA[b2*63 + 3*(e>>1) + (e&1)];
    }
    if (tid < B*2) {
        const float* g = sA + tid*63;
        float xmn = 3.4e38f, xmx = -3.4e38f, ymn = 3.4e38f, ymx = -3.4e38f, nv = 0.f;
        unsigned m = 0;
        #pragma unroll
        for (int k = 0; k < NKPT; k++) {
            float x = g[3*k], y = g[3*k+1];
            xmn = fminf(xmn, x); xmx = fmaxf(xmx, x);
            ymn = fminf(ymn, y); ymx = fmaxf(ymx, y);
            if (g[3*k+2] > 0.f) { nv += 1.f; m |= (1u << k); }
        }
        float s2 = fmaxf((xmx - xmn) * (ymx - ymn), 1.f);
        s_nc[tid]    = -1.442695040888963f / (2.f * s2 * 0.01f);
        s_nvinv[tid] = 1.f / fmaxf(nv, 1.f);
        s_mask[tid]  = m;
    }
    __syncthreads();

    const int a = blockIdx.x * 128 + tid;
    const bool valid = (a < A);

    float ax[NKPT], ay[NKPT];
    bool inside = true;

    if (valid) {
        int j   = a % NANCH;
        int pos = a / NANCH;
        int ix  = pos % feat_w;
        int iy  = pos / feat_w;
        float shx = (float)((double)ix * (256.0 / (double)feat_w));
        float shy = (float)((double)iy * (256.0 / (double)feat_h));

        int si = j >> 2, oi = j & 3;
        float sc = (si == 0) ? 0.25f : ((si == 1) ? 0.5f : 1.0f);
        double th = (double)(oi * 90) * (M_PI / 180.0);
        float cth = (float)cos(th), sth = (float)sin(th);

        double mx = 0.0, my = 0.0;
        #pragma unroll
        for (int k = 0; k < NKPT; k++) { mx += (double)c_ref[2*k]; my += (double)c_ref[2*k+1]; }
        float cx = (float)(mx / 21.0), cy = (float)(my / 21.0);

        #pragma unroll
        for (int k = 0; k < NKPT; k++) {
            float vx = c_ref[2*k]   - cx;
            float vy = c_ref[2*k+1] - cy;
            float px = cx + sc * (vx*cth - vy*sth) + shx;
            float py = cy + sc * (vx*sth + vy*cth) + shy;
            ax[k] = px; ay[k] = py;
            sA[tid*43 + 2*k]   = px;
            sA[tid*43 + 2*k+1] = py;
            inside = inside && (px >= 0.f) && (py >= 0.f) && (px < 256.f) && (py < 256.f);
        }
        out[(size_t)A*42 + a] = inside ? 1.f : 0.f;
    }
    __syncthreads();

    // 3) cooperative float4 anchor store (get big stores in flight early)
    {
        int a0  = blockIdx.x * 128;
        int cnt = min(128, A - a0);
        int nfl = cnt * 42;
        int nf4 = nfl >> 2;                     // base a0*42 is 4-aligned
        float4* op = (float4*)(out + (size_t)a0*42);
        for (int f = tid; f < nf4; f += 128) {
            int o = f << 2;
            int la = o / 42;
            int e  = o - la*42;
            float4 v;
            float* vv = &v.x;
            #pragma unroll
            for (int i = 0; i < 4; i++) {
                vv[i] = sA[la*43 + e];
                if (++e == 42) { e = 0; ++la; }
            }
            op[f] = v;
        }
        for (int o = (nf4 << 2) + tid; o < nfl; o += 128) {
            int la = o / 42, e = o - la*42;
            out[(size_t)a0*42 + o] = sA[la*43 + e];
        }
    }

    // 4) OKS + labels + decision codes
    if (valid) {
        float* labels = out + (size_t)A*43;
        for (int b = 0; b < B; b++) {
            const float* g0 = s_gxy + (b*2)*42;
            const float* g1 = g0 + 42;
            float nc0 = s_nc[2*b], nc1 = s_nc[2*b+1];
            unsigned m0 = s_mask[2*b], m1 = s_mask[2*b+1];
            float acc0 = 0.f, acc1 = 0.f;
            #pragma unroll
            for (int k = 0; k < NKPT; k++) {
                float dx0 = ax[k] - g0[2*k];
                float dy0 = ay[k] - g0[2*k+1];
                float e0  = ex2f((dx0*dx0 + dy0*dy0) * nc0);
                if (m0 & (1u << k)) acc0 += e0;
                float dx1 = ax[k] - g1[2*k];
                float dy1 = ay[k] - g1[2*k+1];
                float e1  = ex2f((dx1*dx1 + dy1*dy1) * nc1);
                if (m1 & (1u << k)) acc1 += e1;
            }
            float sim0 = acc0 * s_nvinv[2*b];
            float sim1 = acc1 * s_nvinv[2*b+1];

            bool am0 = (sim0 >= sim1);
            float mxs = fmaxf(sim0, sim1);
            bool right = am0  && (mxs > 0.5f) && (s_ht[2*b]   == 1) && inside;
            bool left  = !am0 && (mxs > 0.5f) && (s_ht[2*b+1] == 1) && inside;

            float l0, l1, l2;
            if (inside) {
                l0 = left  ? 1.f : 0.f;
                l2 = right ? 1.f : 0.f;
                l1 = (!left && !right) ? 1.f : 0.f;
            } else {
                l0 = l1 = l2 = -1.f;
            }
            size_t lb = ((size_t)b*A + a) * 3;
            labels[lb]   = l0;
            labels[lb+1] = l1;
            labels[lb+2] = l2;

            g_dec[(size_t)b*A + a] = inside ? (right ? 2 : (left ? 1 : 0)) : 3;
        }
    }
}

// -----------------------------------------------------------------------------
// Phase C: tile of CTILE anchors staged in smem, all B rows emitted as
// streaming float4 stores. Anchors are read from global ONCE per tile.
// -----------------------------------------------------------------------------
__global__ void __launch_bounds__(256) phaseC_kernel(
    const float* __restrict__ gt,       // [B,2,21,3]
    const float* __restrict__ anchors,  // [A,21,2] (== out base)
    float* __restrict__ ofs,            // [B,A,21,2]
    int A, int B)
{
    __shared__ float   sA[CTILE*42];
    __shared__ float   sg[BMAX*2*42];
    __shared__ uint8_t sdec[BMAX*CTILE];

    const int tid = threadIdx.x;
    const int a0  = blockIdx.x * CTILE;
    const int cnt = min(CTILE, A - a0);
    const int nfl = cnt * 42;
    const int nf4 = nfl >> 2;                  // a0*42 is 4-aligned (a0 mult of 64)

    // stage anchors (float4 loads)
    const float* ap = anchors + (size_t)a0*42;
    for (int f = tid; f < nf4; f += 256) ((float4*)sA)[f] = ((const float4*)ap)[f];
    for (int i = (nf4 << 2) + tid; i < nfl; i += 256) sA[i] = ap[i];

    // stage packed gt xy
    for (int i = tid; i < B*2*42; i += 256) {
        int b2 = i / 42, e = i - b2*42;
        sg[i] = gt[b2*63 + 3*(e>>1) + (e&1)];
    }
    // stage decision bytes
    for (int i = tid; i < B*CTILE; i += 256) {
        int b = i / CTILE, la = i - b*CTILE;
        if (la < cnt) sdec[i] = g_dec[(size_t)b*A + a0 + la];
    }
    __syncthreads();

    for (int b = 0; b < B; b++) {
        float4* op = (float4*)(ofs + ((size_t)b*A + a0)*42);
        const float*   g0 = sg + b*84;          // hand0; hand1 at +42
        const uint8_t* dp = sdec + b*CTILE;

        for (int f = tid; f < nf4; f += 256) {
            int o  = f << 2;
            int la = o / 42;
            int e  = o - la*42;
            float4 v;
            float* vv = &v.x;
            #pragma unroll
            for (int i = 0; i < 4; i++) {
                uint8_t d  = dp[la];
                float  av  = sA[la*42 + e];
                int   off  = (d == 1) ? 42 : 0;
                float  tg  = g0[off + e];
                float  t   = (d == 1 || d == 2) ? tg : 0.f;
                float  r   = t - av;
                vv[i] = (d == 3) ? 0.f : r;
                if (++e == 42) { e = 0; ++la; }
            }
            __stcs(op + f, v);                  // streaming: don't pollute L2
        }
        for (int o = (nf4 << 2) + tid; o < nfl; o += 256) {
            int la = o / 42, e = o - la*42;
            uint8_t d = dp[la];
            float av = sA[la*42 + e];
            int off = (d == 1) ? 42 : 0;
            float t = (d == 1 || d == 2) ? g0[off + e] : 0.f;
            float r = (d == 3) ? 0.f : (t - av);
            ofs[((size_t)b*A + a0)*42 + o] = r;
        }
    }
}

extern "C" void kernel_launch(void* const* d_in, const int* in_sizes, int n_in,
                              void* d_out, int out_size)
{
    const float* gt = (const float*)d_in[0];
    const int*   ht = (const int*)d_in[1];
    const int*   fh = (n_in >= 4) ? (const int*)d_in[2] : nullptr;
    const int*   fw = (n_in >= 4) ? (const int*)d_in[3] : nullptr;
    float* out = (float*)d_out;

    int B = in_sizes[0] / (2*NKPT*3);
    if (B < 1) B = 1;
    if (B > BMAX) B = BMAX;
    long long denom = 42 + 1 + 3LL*B + 42LL*B;
    int A = (int)((long long)out_size / denom);

    int blocksA = (A + 127) / 128;
    phaseA_kernel<<<blocksA, 128>>>(gt, ht, fh, fw, out, B, A);

    float* ofs = out + (size_t)A*43 + (size_t)3*B*A;
    int blocksC = (A + CTILE - 1) / CTILE;
    phaseC_kernel<<<blocksC, 256>>>(gt, out, ofs, A, B);
}